// round 3
// baseline (speedup 1.0000x reference)
#include <cuda_runtime.h>
#include <cstdint>

#define N_NODES 50000
#define HID 256
#define NCLS 40
#define E_MAX 1000000
#define FULL_MASK 0xFFFFFFFFu

// ---------------- scratch (device globals; no allocations allowed) ----------
__device__ float g_h[(size_t)N_NODES * HID];     // h = x @ W for current layer
__device__ float g_bufA[(size_t)N_NODES * HID];  // layer outputs (ping)
__device__ float g_bufB[(size_t)N_NODES * HID];  // layer outputs (pong)
__device__ float g_ssrc[N_NODES];
__device__ float g_sdst[N_NODES];
__device__ int   g_deg[N_NODES];
__device__ int   g_offs[N_NODES + 1];
__device__ int   g_cursor[N_NODES];
__device__ int   g_csr[E_MAX];                   // src node per CSR slot (sorted by dst)
__device__ int   g_idx64;                        // 1 if edge_index is int64, 0 if int32

// ---------------- edge index access (dtype-agnostic) ------------------------
__device__ __forceinline__ int edge_val(const void* e, long long i) {
    return g_idx64 ? (int)((const long long*)e)[i] : ((const int*)e)[i];
}

// ---------------- CSR construction ------------------------------------------
__global__ void detect_and_init(const void* edge, int E) {
    int idx = blockIdx.x * blockDim.x + threadIdx.x;
    if (idx < N_NODES) g_deg[idx] = 1;  // self-loop contributes 1 to each node
    if (idx == 0) {
        // If data is really int32, an int64 view packs two random node ids;
        // the high word is nonzero with prob ~1-2e-5 per entry, so 1024
        // samples all being valid node ids identifies int64 definitively.
        const long long* p = (const long long*)edge;
        int n = E < 1024 ? E : 1024;
        int ok = 1;
        for (int i = 0; i < n; i++) {
            long long v = p[i];
            if (v < 0 || v >= N_NODES) { ok = 0; break; }
        }
        g_idx64 = ok;
    }
}

__global__ void hist_kernel(const void* edge, int E) {
    int i = blockIdx.x * blockDim.x + threadIdx.x;
    if (i < E) {
        int d = edge_val(edge, (long long)E + i);  // dst row
        atomicAdd(&g_deg[d], 1);
    }
}

// single-block exclusive scan over g_deg -> g_offs (+ copy to g_cursor)
__global__ void scan_kernel() {
    __shared__ int sh[1024];
    __shared__ int s_run;
    int t = threadIdx.x;
    if (t == 0) s_run = 0;
    __syncthreads();
    for (int base = 0; base < N_NODES; base += 1024) {
        int i = base + t;
        int v = (i < N_NODES) ? g_deg[i] : 0;
        sh[t] = v;
        __syncthreads();
        #pragma unroll
        for (int off = 1; off < 1024; off <<= 1) {
            int add = (t >= off) ? sh[t - off] : 0;
            __syncthreads();
            sh[t] += add;
            __syncthreads();
        }
        int excl = sh[t] - v;
        if (i < N_NODES) {
            int o = s_run + excl;
            g_offs[i] = o;
            g_cursor[i] = o;
        }
        __syncthreads();
        if (t == 1023) s_run += sh[1023];
        __syncthreads();
    }
    if (t == 0) g_offs[N_NODES] = s_run;
}

__global__ void scatter_kernel(const void* edge, int E) {
    int i = blockIdx.x * blockDim.x + threadIdx.x;
    if (i < E) {
        int s = edge_val(edge, i);
        int d = edge_val(edge, (long long)E + i);
        int pos = atomicAdd(&g_cursor[d], 1);
        g_csr[pos] = s;
    } else if (i < E + N_NODES) {
        int v = i - E;  // self-loop
        int pos = atomicAdd(&g_cursor[v], 1);
        g_csr[pos] = v;
    }
}

// ---------------- fp32 SGEMM: C[M,Ncols] = A[M,K] @ B[K,Ncols] ---------------
template <bool BIAS, bool RELU>
__global__ __launch_bounds__(256)
void sgemm128(const float* __restrict__ A, const float* __restrict__ B,
              const float* __restrict__ bias, float* __restrict__ C,
              int M, int Ncols, int K) {
    const int BM = 128, BN = 128, BK = 16;
    __shared__ float As[BK][BM + 4];
    __shared__ float Bs[BK][BN + 4];
    int tid  = threadIdx.x;
    int brow = blockIdx.x * BM;
    int bcol = blockIdx.y * BN;
    int tr = (tid >> 4) * 8;   // 0..120
    int tc = (tid & 15) * 8;   // 0..120

    float acc[8][8];
    #pragma unroll
    for (int i = 0; i < 8; i++)
        #pragma unroll
        for (int j = 0; j < 8; j++) acc[i][j] = 0.f;

    for (int k0 = 0; k0 < K; k0 += BK) {
        // A tile: 128x16 = 512 float4, 2 per thread
        #pragma unroll
        for (int li = 0; li < 2; li++) {
            int id = tid * 2 + li;
            int r  = id >> 2;
            int cv = (id & 3) * 4;
            float4 v = make_float4(0.f, 0.f, 0.f, 0.f);
            int gr = brow + r;
            if (gr < M) v = *reinterpret_cast<const float4*>(A + (size_t)gr * K + k0 + cv);
            As[cv + 0][r] = v.x; As[cv + 1][r] = v.y;
            As[cv + 2][r] = v.z; As[cv + 3][r] = v.w;
        }
        // B tile: 16x128 = 512 float4, 2 per thread
        #pragma unroll
        for (int li = 0; li < 2; li++) {
            int id = tid * 2 + li;
            int r  = id >> 5;
            int cv = (id & 31) * 4;
            int gc = bcol + cv;
            float4 v = make_float4(0.f, 0.f, 0.f, 0.f);
            if (gc + 3 < Ncols) {
                v = *reinterpret_cast<const float4*>(B + (size_t)(k0 + r) * Ncols + gc);
            } else if (gc < Ncols) {
                float tq[4] = {0.f, 0.f, 0.f, 0.f};
                for (int q = 0; q < 4; q++)
                    if (gc + q < Ncols) tq[q] = B[(size_t)(k0 + r) * Ncols + gc + q];
                v = make_float4(tq[0], tq[1], tq[2], tq[3]);
            }
            *reinterpret_cast<float4*>(&Bs[r][cv]) = v;
        }
        __syncthreads();
        #pragma unroll
        for (int kk = 0; kk < BK; kk++) {
            float a[8], b[8];
            #pragma unroll
            for (int i = 0; i < 8; i++) a[i] = As[kk][tr + i];
            #pragma unroll
            for (int j = 0; j < 8; j++) b[j] = Bs[kk][tc + j];
            #pragma unroll
            for (int i = 0; i < 8; i++)
                #pragma unroll
                for (int j = 0; j < 8; j++) acc[i][j] += a[i] * b[j];
        }
        __syncthreads();
    }
    #pragma unroll
    for (int i = 0; i < 8; i++) {
        int gr = brow + tr + i;
        if (gr >= M) continue;
        #pragma unroll
        for (int j = 0; j < 8; j++) {
            int gc = bcol + tc + j;
            if (gc >= Ncols) continue;
            float v = acc[i][j];
            if (BIAS) v += bias[gc];
            if (RELU) v = fmaxf(v, 0.f);
            C[(size_t)gr * Ncols + gc] = v;
        }
    }
}

// ---------------- per-node attention scores: s = h @ a -----------------------
__global__ void scores_kernel(const float* __restrict__ h,
                              const float* __restrict__ asrc,
                              const float* __restrict__ adst) {
    int warp = (blockIdx.x * blockDim.x + threadIdx.x) >> 5;
    int lane = threadIdx.x & 31;
    if (warp >= N_NODES) return;
    const float4* hp = reinterpret_cast<const float4*>(h + (size_t)warp * HID);
    const float4* a1 = reinterpret_cast<const float4*>(asrc);
    const float4* a2 = reinterpret_cast<const float4*>(adst);
    float s1 = 0.f, s2 = 0.f;
    #pragma unroll
    for (int i = 0; i < 2; i++) {
        int idx = lane + i * 32;   // 64 float4 per row
        float4 v = hp[idx], w1 = a1[idx], w2 = a2[idx];
        s1 += v.x * w1.x + v.y * w1.y + v.z * w1.z + v.w * w1.w;
        s2 += v.x * w2.x + v.y * w2.y + v.z * w2.z + v.w * w2.w;
    }
    #pragma unroll
    for (int o = 16; o > 0; o >>= 1) {
        s1 += __shfl_xor_sync(FULL_MASK, s1, o);
        s2 += __shfl_xor_sync(FULL_MASK, s2, o);
    }
    if (lane == 0) { g_ssrc[warp] = s1; g_sdst[warp] = s2; }
}

// ---------------- GAT aggregation: one warp per dst node ---------------------
template <bool RELU>
__global__ void aggregate_kernel(const float* __restrict__ h,
                                 const float* __restrict__ bias,
                                 float* __restrict__ out) {
    int d    = (blockIdx.x * blockDim.x + threadIdx.x) >> 5;
    int lane = threadIdx.x & 31;
    if (d >= N_NODES) return;
    int start = g_offs[d];
    int end   = g_offs[d + 1];
    float sd  = g_sdst[d];

    // pass 1: segment max of leaky-relu scores
    float m = -1e30f;
    for (int i = start + lane; i < end; i += 32) {
        int s = g_csr[i];
        float sc = g_ssrc[s] + sd;
        sc = sc > 0.f ? sc : 0.2f * sc;
        m = fmaxf(m, sc);
    }
    #pragma unroll
    for (int o = 16; o > 0; o >>= 1) m = fmaxf(m, __shfl_xor_sync(FULL_MASK, m, o));

    // pass 2: exp weights, denom, and weighted feature accumulation
    float acc[8] = {0.f, 0.f, 0.f, 0.f, 0.f, 0.f, 0.f, 0.f};
    float denom = 0.f;
    for (int base = start; base < end; base += 32) {
        int i = base + lane;
        float w = 0.f;
        int s = 0;
        if (i < end) {
            s = g_csr[i];
            float sc = g_ssrc[s] + sd;
            sc = sc > 0.f ? sc : 0.2f * sc;
            w = __expf(sc - m);
        }
        denom += w;
        int cnt = min(32, end - base);
        for (int j = 0; j < cnt; j++) {
            float wj = __shfl_sync(FULL_MASK, w, j);
            int   sj = __shfl_sync(FULL_MASK, s, j);
            const float4* hp = reinterpret_cast<const float4*>(h + (size_t)sj * HID);
            float4 v0 = hp[lane * 2];
            float4 v1 = hp[lane * 2 + 1];
            acc[0] += wj * v0.x; acc[1] += wj * v0.y;
            acc[2] += wj * v0.z; acc[3] += wj * v0.w;
            acc[4] += wj * v1.x; acc[5] += wj * v1.y;
            acc[6] += wj * v1.z; acc[7] += wj * v1.w;
        }
    }
    #pragma unroll
    for (int o = 16; o > 0; o >>= 1) denom += __shfl_xor_sync(FULL_MASK, denom, o);
    float inv = 1.f / (denom + 1e-16f);

    float*       op = out  + (size_t)d * HID + lane * 8;
    const float* bp = bias + lane * 8;
    #pragma unroll
    for (int k = 0; k < 8; k++) {
        float v = acc[k] * inv + bp[k];
        if (RELU) v = fmaxf(v, 0.f);
        op[k] = v;
    }
}

// ---------------- launch ------------------------------------------------------
extern "C" void kernel_launch(void* const* d_in, const int* in_sizes, int n_in,
                              void* d_out, int out_size) {
    const float* x    = (const float*)d_in[0];
    const void*  edge = d_in[1];
    const float* W1 = (const float*)d_in[2];
    const float* as1 = (const float*)d_in[3];
    const float* ad1 = (const float*)d_in[4];
    const float* b1 = (const float*)d_in[5];
    const float* W2 = (const float*)d_in[6];
    const float* as2 = (const float*)d_in[7];
    const float* ad2 = (const float*)d_in[8];
    const float* b2 = (const float*)d_in[9];
    const float* W3 = (const float*)d_in[10];
    const float* as3 = (const float*)d_in[11];
    const float* ad3 = (const float*)d_in[12];
    const float* b3 = (const float*)d_in[13];
    const float* Wp = (const float*)d_in[14];
    const float* bp = (const float*)d_in[15];
    const float* Wr = (const float*)d_in[16];
    const float* br = (const float*)d_in[17];
    float* out = (float*)d_out;

    int E = in_sizes[1] / 2;

    float *h, *bufA, *bufB;
    cudaGetSymbolAddress((void**)&h,    g_h);
    cudaGetSymbolAddress((void**)&bufA, g_bufA);
    cudaGetSymbolAddress((void**)&bufB, g_bufB);

    const int TPB = 256;
    int nodeBlocks = (N_NODES + TPB - 1) / TPB;
    int warpNodeBlocks = (N_NODES * 32 + TPB - 1) / TPB;   // one warp per node

    // --- CSR build ---
    detect_and_init<<<nodeBlocks, TPB>>>(edge, E);
    hist_kernel<<<(E + TPB - 1) / TPB, TPB>>>(edge, E);
    scan_kernel<<<1, 1024>>>();
    scatter_kernel<<<(E + N_NODES + TPB - 1) / TPB, TPB>>>(edge, E);

    dim3 gw((N_NODES + 127) / 128, (HID + 127) / 128);     // 391 x 2
    dim3 gro((N_NODES + 127) / 128, 1);                    // readout: 40 cols

    // --- layer 1 ---
    sgemm128<false, false><<<gw, TPB>>>(x, W1, nullptr, h, N_NODES, HID, HID);
    scores_kernel<<<warpNodeBlocks, TPB>>>(h, as1, ad1);
    aggregate_kernel<true><<<warpNodeBlocks, TPB>>>(h, b1, bufA);
    // --- layer 2 ---
    sgemm128<false, false><<<gw, TPB>>>(bufA, W2, nullptr, h, N_NODES, HID, HID);
    scores_kernel<<<warpNodeBlocks, TPB>>>(h, as2, ad2);
    aggregate_kernel<true><<<warpNodeBlocks, TPB>>>(h, b2, bufB);
    // --- layer 3 (no relu) ---
    sgemm128<false, false><<<gw, TPB>>>(bufB, W3, nullptr, h, N_NODES, HID, HID);
    scores_kernel<<<warpNodeBlocks, TPB>>>(h, as3, ad3);
    aggregate_kernel<false><<<warpNodeBlocks, TPB>>>(h, b3, bufA);
    // --- post1: Linear + ReLU ---
    sgemm128<true, true><<<gw, TPB>>>(bufA, Wp, bp, bufB, N_NODES, HID, HID);
    // --- readout: Linear(H, C) ---
    sgemm128<true, false><<<gro, TPB>>>(bufB, Wr, br, out, N_NODES, NCLS, HID);
}